// round 14
// baseline (speedup 1.0000x reference)
#include <cuda_runtime.h>
#include <cuda_fp16.h>
#include <math.h>
#include <stdint.h>

#define BB 8
#define NN 16384
#define PP 512
#define DD 64
#define PT 128                  /* p per CTA (8 warps x 16) */
#define NSPLIT 16
#define NPER (NN / NSPLIT)      /* 1024 */
#define CHN 64                  /* n per chunk */
#define NCHUNK (NPER / CHN)     /* 16 */
#define PITCHB 80               /* bytes per n-row in smem (64 data + 16 pad) */
#define BUFB (CHN * PITCHB)     /* 5120 bytes per buffer */
#define X2OFF (2 * BUFB)        /* x2 buffers (2 x 256B) */
#define SXOFF (X2OFF + 512)     /* sx buffers (2 x 256B) */
#define SMTOT (SXOFF + 512)
#define MARGIN 4.0f             /* >= 2*eps for int8 quantized approx */
#define CAP 512
#define SSTRIDE (NN / 64)       /* 256: global sample stride for prepass */
#define QS (-2.0f / 127.0f)     /* epilogue scale: t = x2 + idot*sx*QS */

__device__ unsigned short g_pq[PP * 32];   /* int8 protos packed 2/ushort [p][d] */
__device__ float g_pn[PP * DD];            /* fp32 normalized protos (refine) */
__device__ float g_p2[PP];
__device__ unsigned char g_xq[BB * NN * DD]; /* int8 x [b][n][d] */
__device__ float g_xs[BB * NN];            /* per-row x scale (max|x|/127) */
__device__ float g_x2[BB * NN];
__device__ unsigned g_thr[BB * PP];        /* shared best sq (float bits) */
__device__ int g_cnt[BB * PP];
__device__ int g_cand[BB * PP * CAP];

__device__ __forceinline__ void mma_s8(int& d0, int& d1, int& d2, int& d3,
                                       uint32_t a0, uint32_t a1, uint32_t a2, uint32_t a3,
                                       uint32_t b0, uint32_t b1) {
    asm("mma.sync.aligned.m16n8k32.row.col.s32.s8.s8.s32 "
        "{%0,%1,%2,%3}, {%4,%5,%6,%7}, {%8,%9}, {%0,%1,%2,%3};"
        : "+r"(d0), "+r"(d1), "+r"(d2), "+r"(d3)
        : "r"(a0), "r"(a1), "r"(a2), "r"(a3), "r"(b0), "r"(b1));
}
__device__ __forceinline__ void ldmx4(uint32_t a, uint32_t& r0, uint32_t& r1,
                                      uint32_t& r2, uint32_t& r3) {
    asm volatile("ldmatrix.sync.aligned.m8n8.x4.shared.b16 {%0,%1,%2,%3}, [%4];"
                 : "=r"(r0), "=r"(r1), "=r"(r2), "=r"(r3) : "r"(a));
}
__device__ __forceinline__ void cpa16(uint32_t s, const void* g) {
    asm volatile("cp.async.cg.shared.global [%0], [%1], 16;" :: "r"(s), "l"(g));
}
__device__ __forceinline__ uint32_t smem_u32(const void* p) {
    uint32_t a;
    asm("{ .reg .u64 t; cvta.to.shared.u64 t, %1; cvt.u32.u64 %0, t; }"
        : "=r"(a) : "l"(p));
    return a;
}
__device__ __forceinline__ unsigned short pack8(int q0, int q1) {
    return (unsigned short)((q0 & 0xFF) | ((q1 & 0xFF) << 8));
}

/* ------------------------------------------------------------------ */
/* fused prep (blocks 0..63) + conv (blocks 64.., 4 rows per warp).   */
__global__ void prep_conv_kernel(const float* __restrict__ proto,
                                 const float* __restrict__ x) {
    if (blockIdx.x < 64) {
        int t = blockIdx.x * blockDim.x + threadIdx.x;
        if (t < BB * PP) { g_cnt[t] = 0; g_thr[t] = 0x7f800000u; }

        int gw = t >> 5, lane = t & 31;
        if (gw >= PP) return;
        float2 v = ((const float2*)(proto + gw * DD))[lane];
        float s = v.x * v.x + v.y * v.y;
        #pragma unroll
        for (int o = 16; o; o >>= 1) s += __shfl_xor_sync(0xFFFFFFFFu, s, o);
        float inv = 1.0f / fmaxf(sqrtf(s), 1e-12f);
        float a = v.x * inv, b = v.y * inv;

        g_pq[gw * 32 + lane] = pack8(__float2int_rn(a * 127.0f),
                                     __float2int_rn(b * 127.0f));
        g_pn[gw * DD + 2 * lane + 0] = a;
        g_pn[gw * DD + 2 * lane + 1] = b;

        float q = a * a + b * b;
        #pragma unroll
        for (int o = 16; o; o >>= 1) q += __shfl_xor_sync(0xFFFFFFFFu, q, o);
        if (lane == 0) g_p2[gw] = q;
    } else {
        /* conv: each warp quantizes 4 rows (MLP=4) */
        const int lane = threadIdx.x & 31;
        const int row0 = ((int)(blockIdx.x - 64) * 8 + (threadIdx.x >> 5)) * 4;
        if (row0 >= BB * NN) return;

        float2 v[4];
        #pragma unroll
        for (int r = 0; r < 4; r++)
            v[r] = ((const float2*)(x + (size_t)(row0 + r) * DD))[lane];

        float s[4], m[4];
        #pragma unroll
        for (int r = 0; r < 4; r++) {
            s[r] = fmaf(v[r].x, v[r].x, v[r].y * v[r].y);
            m[r] = fmaxf(fabsf(v[r].x), fabsf(v[r].y));
        }
        #pragma unroll
        for (int o = 16; o; o >>= 1) {
            #pragma unroll
            for (int r = 0; r < 4; r++) {
                s[r] += __shfl_xor_sync(0xFFFFFFFFu, s[r], o);
                m[r] = fmaxf(m[r], __shfl_xor_sync(0xFFFFFFFFu, m[r], o));
            }
        }
        #pragma unroll
        for (int r = 0; r < 4; r++) {
            float mm = fmaxf(m[r], 1e-30f);
            float invq = 127.0f / mm;
            ((unsigned short*)g_xq)[(size_t)(row0 + r) * 32 + lane] =
                pack8(__float2int_rn(v[r].x * invq), __float2int_rn(v[r].y * invq));
            if (lane == r) {
                g_x2[row0 + r] = s[r];
                g_xs[row0 + r] = mm / 127.0f;
            }
        }
    }
}

/* ------------------------------------------------------------------ */
/* main: int8 m16n8k32 GEMM, cp.async double buffer, 2x MMA ILP.
   64-sample strided prepass + chip-wide shared thresholds (g_thr),
   then conservative proxy-filtered candidate collection.              */
__global__ void __launch_bounds__(256, 4)
main_kernel() {
    __shared__ __align__(16) unsigned char sbuf[SMTOT];
    const uint32_t sbase = smem_u32(sbuf);

    const int tid = threadIdx.x;
    const int w = tid >> 5, lane = tid & 31;
    const int g = lane >> 2, tm4 = lane & 3;
    const int bb = blockIdx.z;
    const int p0 = blockIdx.y * PT + w * 16;
    const int n0 = blockIdx.x * NPER;

    /* A fragments (int8 k32): A[kk][r], kk = k-half (0:k0-31, 1:k32-63) */
    uint32_t A0[2][4];
    {
        const unsigned* pq = (const unsigned*)g_pq + (size_t)p0 * 16;
        #pragma unroll
        for (int kk = 0; kk < 2; kk++) {
            A0[kk][0] = __ldg(pq + (size_t)g * 16 + tm4 + kk * 8);
            A0[kk][1] = __ldg(pq + (size_t)(g + 8) * 16 + tm4 + kk * 8);
            A0[kk][2] = __ldg(pq + (size_t)g * 16 + tm4 + 4 + kk * 8);
            A0[kk][3] = __ldg(pq + (size_t)(g + 8) * 16 + tm4 + 4 + kk * 8);
        }
    }
    const float p2a = g_p2[p0 + g];
    const float p2b = g_p2[p0 + g + 8];
    const int bp0 = bb * PP + p0 + g;
    const int bp1 = bp0 + 8;

    const unsigned char* xqB = g_xq + (size_t)bb * NN * DD;
    const unsigned char* xq = xqB + (size_t)n0 * DD;
    const float* x2B = g_x2 + (size_t)bb * NN;
    const float* xsB = g_xs + (size_t)bb * NN;
    const unsigned char* x2g = (const unsigned char*)(x2B + n0);
    const unsigned char* sxg = (const unsigned char*)(xsB + n0);

    const uint32_t lrow = (uint32_t)(lane & 7) * PITCHB + (uint32_t)(lane >> 3) * 16;

    auto stage = [&](int it) {
        const uint32_t sb = sbase + (it & 1) * BUFB;
        const unsigned char* gsrc = xq + (size_t)it * (CHN * DD);
        cpa16(sb + (uint32_t)(tid >> 2) * PITCHB + (uint32_t)(tid & 3) * 16,
              gsrc + (size_t)tid * 16);
        if (tid < 16)
            cpa16(sbase + X2OFF + (it & 1) * 256 + tid * 16,
                  x2g + (size_t)it * 256 + tid * 16);
        else if (tid < 32)
            cpa16(sbase + SXOFF + (it & 1) * 256 + (tid - 16) * 16,
                  sxg + (size_t)it * 256 + (tid - 16) * 16);
        asm volatile("cp.async.commit_group;");
    };

    /* ---- prepass: 64 rows strided across ALL of N ---- */
    {
        int row = tid >> 2, seg = tid & 3;
        cpa16(sbase + (uint32_t)row * PITCHB + (uint32_t)seg * 16,
              xqB + (size_t)row * SSTRIDE * DD + seg * 16);
        if (tid < 64) {
            ((float*)(sbuf + X2OFF))[tid] = x2B[(size_t)tid * SSTRIDE];
            ((float*)(sbuf + SXOFF))[tid] = xsB[(size_t)tid * SSTRIDE];
        }
        asm volatile("cp.async.commit_group;");
        asm volatile("cp.async.wait_group 0;");
        __syncthreads();
    }

    float best0 = __int_as_float(0x7f800000);
    float best1 = __int_as_float(0x7f800000);
    {
        const float* x2s = (const float*)(sbuf + X2OFF);
        const float* sxs = (const float*)(sbuf + SXOFF);
        #pragma unroll
        for (int sub = 0; sub < 8; sub++) {
            uint32_t aA = sbase + (uint32_t)(sub * 8) * PITCHB + lrow;
            uint32_t r0, r1, r2, r3;
            ldmx4(aA, r0, r1, r2, r3);
            int d0 = 0, d1 = 0, d2 = 0, d3 = 0;
            mma_s8(d0, d1, d2, d3, A0[0][0], A0[0][1], A0[0][2], A0[0][3], r0, r1);
            mma_s8(d0, d1, d2, d3, A0[1][0], A0[1][1], A0[1][2], A0[1][3], r2, r3);
            const int nl = sub * 8 + 2 * tm4;
            float x20 = x2s[nl], x21 = x2s[nl + 1];
            float cc0 = sxs[nl] * QS, cc1 = sxs[nl + 1] * QS;
            best0 = fminf(best0, fmaxf(fmaf((float)d0, cc0, x20) + p2a, 0.0f));
            best0 = fminf(best0, fmaxf(fmaf((float)d1, cc1, x21) + p2a, 0.0f));
            best1 = fminf(best1, fmaxf(fmaf((float)d2, cc0, x20) + p2b, 0.0f));
            best1 = fminf(best1, fmaxf(fmaf((float)d3, cc1, x21) + p2b, 0.0f));
        }
        best0 = fminf(best0, __shfl_xor_sync(0xFFFFFFFFu, best0, 1));
        best0 = fminf(best0, __shfl_xor_sync(0xFFFFFFFFu, best0, 2));
        best1 = fminf(best1, __shfl_xor_sync(0xFFFFFFFFu, best1, 1));
        best1 = fminf(best1, __shfl_xor_sync(0xFFFFFFFFu, best1, 2));
    }

    if (tm4 == 0) {
        atomicMin(&g_thr[bp0], __float_as_uint(best0));
        atomicMin(&g_thr[bp1], __float_as_uint(best1));
    }

    float thr0 = best0 + MARGIN;
    float thr1 = best1 + MARGIN;
    float thr0m = thr0 - p2a;
    float thr1m = thr1 - p2b;
    __syncthreads();            /* prepass reads done before restaging buf0 */

    stage(0);

    for (int it = 0; it < NCHUNK; it++) {
        float gt0 = __uint_as_float(__ldcg((const unsigned*)&g_thr[bp0]));
        float gt1 = __uint_as_float(__ldcg((const unsigned*)&g_thr[bp1]));

        if (it + 1 < NCHUNK) {
            stage(it + 1);
            asm volatile("cp.async.wait_group 1;");
        } else {
            asm volatile("cp.async.wait_group 0;");
        }
        best0 = fminf(best0, gt0);
        best1 = fminf(best1, gt1);
        thr0 = best0 + MARGIN; thr0m = thr0 - p2a;
        thr1 = best1 + MARGIN; thr1m = thr1 - p2b;
        __syncthreads();

        const uint32_t sb = sbase + (it & 1) * BUFB;
        const float* x2s = (const float*)(sbuf + X2OFF + (it & 1) * 256);
        const float* sxs = (const float*)(sbuf + SXOFF + (it & 1) * 256);

        #pragma unroll 1
        for (int s2 = 0; s2 < 4; s2++) {
            const int sa = s2 * 2, sbn = s2 * 2 + 1;
            uint32_t aA = sb + (uint32_t)(sa * 8) * PITCHB + lrow;
            uint32_t aB = sb + (uint32_t)(sbn * 8) * PITCHB + lrow;
            uint32_t ra0, ra1, ra2, ra3, rb0, rb1, rb2, rb3;
            ldmx4(aA, ra0, ra1, ra2, ra3);
            ldmx4(aB, rb0, rb1, rb2, rb3);

            int dA0 = 0, dA1 = 0, dA2 = 0, dA3 = 0;
            int dB0 = 0, dB1 = 0, dB2 = 0, dB3 = 0;
            mma_s8(dA0, dA1, dA2, dA3, A0[0][0], A0[0][1], A0[0][2], A0[0][3], ra0, ra1);
            mma_s8(dB0, dB1, dB2, dB3, A0[0][0], A0[0][1], A0[0][2], A0[0][3], rb0, rb1);
            mma_s8(dA0, dA1, dA2, dA3, A0[1][0], A0[1][1], A0[1][2], A0[1][3], ra2, ra3);
            mma_s8(dB0, dB1, dB2, dB3, A0[1][0], A0[1][1], A0[1][2], A0[1][3], rb2, rb3);

            #pragma unroll
            for (int half = 0; half < 2; half++) {
                const int sub = half ? sbn : sa;
                int d0 = half ? dB0 : dA0, d1 = half ? dB1 : dA1;
                int d2 = half ? dB2 : dA2, d3 = half ? dB3 : dA3;
                const int nl = sub * 8 + 2 * tm4;
                float x20 = x2s[nl];
                float x21 = x2s[nl + 1];
                float cc0 = sxs[nl] * QS;
                float cc1 = sxs[nl + 1] * QS;
                float t0 = fmaf((float)d0, cc0, x20);
                float t1 = fmaf((float)d1, cc1, x21);
                float t2 = fmaf((float)d2, cc0, x20);
                float t3 = fmaf((float)d3, cc1, x21);
                if (fminf(t0, t1) < thr0m || fminf(t2, t3) < thr1m) {
                    const int nglob = n0 + it * CHN + nl;
                    float s00 = fmaxf(t0 + p2a, 0.0f);
                    float s01 = fmaxf(t1 + p2a, 0.0f);
                    float s10 = fmaxf(t2 + p2b, 0.0f);
                    float s11 = fmaxf(t3 + p2b, 0.0f);
                    if (s00 < thr0) {
                        if (s00 < best0) {
                            best0 = s00; thr0 = s00 + MARGIN; thr0m = thr0 - p2a;
                            atomicMin(&g_thr[bp0], __float_as_uint(best0));
                        }
                        int sl = atomicAdd(&g_cnt[bp0], 1);
                        if (sl < CAP) g_cand[bp0 * CAP + sl] = nglob;
                    }
                    if (s01 < thr0) {
                        if (s01 < best0) {
                            best0 = s01; thr0 = s01 + MARGIN; thr0m = thr0 - p2a;
                            atomicMin(&g_thr[bp0], __float_as_uint(best0));
                        }
                        int sl = atomicAdd(&g_cnt[bp0], 1);
                        if (sl < CAP) g_cand[bp0 * CAP + sl] = nglob + 1;
                    }
                    if (s10 < thr1) {
                        if (s10 < best1) {
                            best1 = s10; thr1 = s10 + MARGIN; thr1m = thr1 - p2b;
                            atomicMin(&g_thr[bp1], __float_as_uint(best1));
                        }
                        int sl = atomicAdd(&g_cnt[bp1], 1);
                        if (sl < CAP) g_cand[bp1 * CAP + sl] = nglob;
                    }
                    if (s11 < thr1) {
                        if (s11 < best1) {
                            best1 = s11; thr1 = s11 + MARGIN; thr1m = thr1 - p2b;
                            atomicMin(&g_thr[bp1], __float_as_uint(best1));
                        }
                        int sl = atomicAdd(&g_cnt[bp1], 1);
                        if (sl < CAP) g_cand[bp1 * CAP + sl] = nglob + 1;
                    }
                }
            }
        }
        __syncthreads();
    }
}

/* ------------------------------------------------------------------ */
/* refine: warp per (b,p); lane-per-candidate exact fp32 recompute. */
__global__ void refine_kernel(const float* __restrict__ x, float* __restrict__ out) {
    __shared__ float ps[8][DD];
    const int wid = threadIdx.x >> 5;
    const int lane = threadIdx.x & 31;
    const int pair = blockIdx.x * 8 + wid;
    const int bb = pair / PP, p = pair % PP;

    ((float2*)ps[wid])[lane] = ((const float2*)(g_pn + (size_t)p * DD))[lane];
    __syncwarp();
    const float p2 = g_p2[p];
    int cnt = g_cnt[pair];
    if (cnt > CAP) cnt = CAP;

    unsigned long long bestk = 0xFFFFFFFFFFFFFFFFull;
    for (int base = 0; base < cnt; base += 32) {
        int i = base + lane;
        if (i < cnt) {
            int n = g_cand[pair * CAP + i];
            const float4* xr = (const float4*)(x + ((size_t)bb * NN + n) * DD);
            float dot = 0.0f, x2 = 0.0f;
            #pragma unroll
            for (int c = 0; c < 16; c++) {
                float4 xv = __ldg(xr + c);
                float4 pv = ((const float4*)ps[wid])[c];
                dot = fmaf(xv.x, pv.x, dot); dot = fmaf(xv.y, pv.y, dot);
                dot = fmaf(xv.z, pv.z, dot); dot = fmaf(xv.w, pv.w, dot);
                x2 = fmaf(xv.x, xv.x, x2); x2 = fmaf(xv.y, xv.y, x2);
                x2 = fmaf(xv.z, xv.z, x2); x2 = fmaf(xv.w, xv.w, x2);
            }
            float sq = fmaxf(x2 - 2.0f * dot + p2, 0.0f);
            unsigned long long key =
                ((unsigned long long)__float_as_uint(sq) << 32) | (unsigned)n;
            if (key < bestk) bestk = key;
        }
    }
    #pragma unroll
    for (int o = 16; o; o >>= 1) {
        unsigned long long ok = __shfl_xor_sync(0xFFFFFFFFu, bestk, o);
        if (ok < bestk) bestk = ok;
    }
    if (lane == 0) {
        float sq = __uint_as_float((unsigned)(bestk >> 32));
        out[pair] = sqrtf(sq + 1e-8f);
        out[BB * PP + pair] = (float)(unsigned)(bestk & 0xFFFFFFFFu);
    }
}

extern "C" void kernel_launch(void* const* d_in, const int* in_sizes, int n_in,
                              void* d_out, int out_size) {
    const float* x = (const float*)d_in[0];
    const float* proto = (const float*)d_in[1];
    float* out = (float*)d_out;

    prep_conv_kernel<<<64 + (BB * NN) / 32, 256>>>(proto, x);
    dim3 grid(NSPLIT, PP / PT, BB);
    main_kernel<<<grid, 256>>>();
    refine_kernel<<<(BB * PP) / 8, 256>>>(x, out);
}

// round 15
// speedup vs baseline: 1.1199x; 1.1199x over previous
#include <cuda_runtime.h>
#include <cuda_fp16.h>
#include <math.h>
#include <stdint.h>

#define BB 8
#define NN 16384
#define PP 512
#define DD 64
#define PT 128                  /* p per CTA (8 warps x 16) */
#define NSPLIT 16
#define NPER (NN / NSPLIT)      /* 1024 */
#define CHN 64                  /* n per chunk */
#define NCHUNK (NPER / CHN)     /* 16 */
#define PITCHB 80               /* bytes per n-row in smem (64 data + 16 pad) */
#define BUFB (CHN * PITCHB)     /* 5120 bytes per buffer */
#define X2OFF (2 * BUFB)        /* x2 buffers (2 x 256B) */
#define SXOFF (X2OFF + 512)     /* sx buffers (2 x 256B) */
#define SMTOT (SXOFF + 512)
#define MARGIN 1.0f             /* 2*eps; eps<=0.5 at >30-sigma via Hoeffding */
#define CAP 512
#define SSTRIDE (NN / 64)       /* 256: global sample stride for prepass */
#define QS (-2.0f / 127.0f)     /* epilogue scale: t = x2 + idot*sx*QS */

__device__ unsigned short g_pq[PP * 32];   /* int8 protos packed 2/ushort [p][d] */
__device__ float g_pn[PP * DD];            /* fp32 normalized protos (refine) */
__device__ float g_p2[PP];
__device__ unsigned char g_xq[BB * NN * DD]; /* int8 x [b][n][d] */
__device__ float g_xs[BB * NN];            /* per-row x scale (max|x|/127) */
__device__ float g_x2[BB * NN];
__device__ unsigned g_thr[BB * PP];        /* shared best sq (float bits) */
__device__ int g_cnt[BB * PP];
__device__ int g_cand[BB * PP * CAP];

__device__ __forceinline__ void mma_s8(int& d0, int& d1, int& d2, int& d3,
                                       uint32_t a0, uint32_t a1, uint32_t a2, uint32_t a3,
                                       uint32_t b0, uint32_t b1) {
    asm("mma.sync.aligned.m16n8k32.row.col.s32.s8.s8.s32 "
        "{%0,%1,%2,%3}, {%4,%5,%6,%7}, {%8,%9}, {%0,%1,%2,%3};"
        : "+r"(d0), "+r"(d1), "+r"(d2), "+r"(d3)
        : "r"(a0), "r"(a1), "r"(a2), "r"(a3), "r"(b0), "r"(b1));
}
__device__ __forceinline__ void ldmx4(uint32_t a, uint32_t& r0, uint32_t& r1,
                                      uint32_t& r2, uint32_t& r3) {
    asm volatile("ldmatrix.sync.aligned.m8n8.x4.shared.b16 {%0,%1,%2,%3}, [%4];"
                 : "=r"(r0), "=r"(r1), "=r"(r2), "=r"(r3) : "r"(a));
}
__device__ __forceinline__ void cpa16(uint32_t s, const void* g) {
    asm volatile("cp.async.cg.shared.global [%0], [%1], 16;" :: "r"(s), "l"(g));
}
__device__ __forceinline__ uint32_t smem_u32(const void* p) {
    uint32_t a;
    asm("{ .reg .u64 t; cvta.to.shared.u64 t, %1; cvt.u32.u64 %0, t; }"
        : "=r"(a) : "l"(p));
    return a;
}
__device__ __forceinline__ unsigned short pack8(int q0, int q1) {
    return (unsigned short)((q0 & 0xFF) | ((q1 & 0xFF) << 8));
}

/* ------------------------------------------------------------------ */
/* fused prep (blocks 0..63) + conv (blocks 64.., 4 rows per warp).   */
__global__ void prep_conv_kernel(const float* __restrict__ proto,
                                 const float* __restrict__ x) {
    if (blockIdx.x < 64) {
        int t = blockIdx.x * blockDim.x + threadIdx.x;
        if (t < BB * PP) { g_cnt[t] = 0; g_thr[t] = 0x7f800000u; }

        int gw = t >> 5, lane = t & 31;
        if (gw >= PP) return;
        float2 v = ((const float2*)(proto + gw * DD))[lane];
        float s = v.x * v.x + v.y * v.y;
        #pragma unroll
        for (int o = 16; o; o >>= 1) s += __shfl_xor_sync(0xFFFFFFFFu, s, o);
        float inv = 1.0f / fmaxf(sqrtf(s), 1e-12f);
        float a = v.x * inv, b = v.y * inv;

        g_pq[gw * 32 + lane] = pack8(__float2int_rn(a * 127.0f),
                                     __float2int_rn(b * 127.0f));
        g_pn[gw * DD + 2 * lane + 0] = a;
        g_pn[gw * DD + 2 * lane + 1] = b;

        float q = a * a + b * b;
        #pragma unroll
        for (int o = 16; o; o >>= 1) q += __shfl_xor_sync(0xFFFFFFFFu, q, o);
        if (lane == 0) g_p2[gw] = q;
    } else {
        /* conv: each warp quantizes 4 rows (MLP=4) */
        const int lane = threadIdx.x & 31;
        const int row0 = ((int)(blockIdx.x - 64) * 8 + (threadIdx.x >> 5)) * 4;
        if (row0 >= BB * NN) return;

        float2 v[4];
        #pragma unroll
        for (int r = 0; r < 4; r++)
            v[r] = ((const float2*)(x + (size_t)(row0 + r) * DD))[lane];

        float s[4], m[4];
        #pragma unroll
        for (int r = 0; r < 4; r++) {
            s[r] = fmaf(v[r].x, v[r].x, v[r].y * v[r].y);
            m[r] = fmaxf(fabsf(v[r].x), fabsf(v[r].y));
        }
        #pragma unroll
        for (int o = 16; o; o >>= 1) {
            #pragma unroll
            for (int r = 0; r < 4; r++) {
                s[r] += __shfl_xor_sync(0xFFFFFFFFu, s[r], o);
                m[r] = fmaxf(m[r], __shfl_xor_sync(0xFFFFFFFFu, m[r], o));
            }
        }
        #pragma unroll
        for (int r = 0; r < 4; r++) {
            float mm = fmaxf(m[r], 1e-30f);
            float invq = 127.0f / mm;
            ((unsigned short*)g_xq)[(size_t)(row0 + r) * 32 + lane] =
                pack8(__float2int_rn(v[r].x * invq), __float2int_rn(v[r].y * invq));
            if (lane == r) {
                g_x2[row0 + r] = s[r];
                g_xs[row0 + r] = mm / 127.0f;
            }
        }
    }
}

/* ------------------------------------------------------------------ */
/* main: int8 m16n8k32 GEMM, cp.async double buffer, 2x MMA ILP.
   64-sample strided prepass + chip-wide shared thresholds (g_thr),
   then conservative proxy-filtered candidate collection.              */
__global__ void __launch_bounds__(256, 4)
main_kernel() {
    __shared__ __align__(16) unsigned char sbuf[SMTOT];
    const uint32_t sbase = smem_u32(sbuf);

    const int tid = threadIdx.x;
    const int w = tid >> 5, lane = tid & 31;
    const int g = lane >> 2, tm4 = lane & 3;
    const int bb = blockIdx.z;
    const int p0 = blockIdx.y * PT + w * 16;
    const int n0 = blockIdx.x * NPER;

    /* A fragments (int8 k32): A[kk][r], kk = k-half (0:k0-31, 1:k32-63) */
    uint32_t A0[2][4];
    {
        const unsigned* pq = (const unsigned*)g_pq + (size_t)p0 * 16;
        #pragma unroll
        for (int kk = 0; kk < 2; kk++) {
            A0[kk][0] = __ldg(pq + (size_t)g * 16 + tm4 + kk * 8);
            A0[kk][1] = __ldg(pq + (size_t)(g + 8) * 16 + tm4 + kk * 8);
            A0[kk][2] = __ldg(pq + (size_t)g * 16 + tm4 + 4 + kk * 8);
            A0[kk][3] = __ldg(pq + (size_t)(g + 8) * 16 + tm4 + 4 + kk * 8);
        }
    }
    const float p2a = g_p2[p0 + g];
    const float p2b = g_p2[p0 + g + 8];
    const int bp0 = bb * PP + p0 + g;
    const int bp1 = bp0 + 8;

    const unsigned char* xqB = g_xq + (size_t)bb * NN * DD;
    const unsigned char* xq = xqB + (size_t)n0 * DD;
    const float* x2B = g_x2 + (size_t)bb * NN;
    const float* xsB = g_xs + (size_t)bb * NN;
    const unsigned char* x2g = (const unsigned char*)(x2B + n0);
    const unsigned char* sxg = (const unsigned char*)(xsB + n0);

    const uint32_t lrow = (uint32_t)(lane & 7) * PITCHB + (uint32_t)(lane >> 3) * 16;

    auto stage = [&](int it) {
        const uint32_t sb = sbase + (it & 1) * BUFB;
        const unsigned char* gsrc = xq + (size_t)it * (CHN * DD);
        cpa16(sb + (uint32_t)(tid >> 2) * PITCHB + (uint32_t)(tid & 3) * 16,
              gsrc + (size_t)tid * 16);
        if (tid < 16)
            cpa16(sbase + X2OFF + (it & 1) * 256 + tid * 16,
                  x2g + (size_t)it * 256 + tid * 16);
        else if (tid < 32)
            cpa16(sbase + SXOFF + (it & 1) * 256 + (tid - 16) * 16,
                  sxg + (size_t)it * 256 + (tid - 16) * 16);
        asm volatile("cp.async.commit_group;");
    };

    /* ---- prepass: 64 rows strided across ALL of N ---- */
    {
        int row = tid >> 2, seg = tid & 3;
        cpa16(sbase + (uint32_t)row * PITCHB + (uint32_t)seg * 16,
              xqB + (size_t)row * SSTRIDE * DD + seg * 16);
        if (tid < 64) {
            ((float*)(sbuf + X2OFF))[tid] = x2B[(size_t)tid * SSTRIDE];
            ((float*)(sbuf + SXOFF))[tid] = xsB[(size_t)tid * SSTRIDE];
        }
        asm volatile("cp.async.commit_group;");
        asm volatile("cp.async.wait_group 0;");
        __syncthreads();
    }

    float best0 = __int_as_float(0x7f800000);
    float best1 = __int_as_float(0x7f800000);
    {
        const float* x2s = (const float*)(sbuf + X2OFF);
        const float* sxs = (const float*)(sbuf + SXOFF);
        #pragma unroll
        for (int sub = 0; sub < 8; sub++) {
            uint32_t aA = sbase + (uint32_t)(sub * 8) * PITCHB + lrow;
            uint32_t r0, r1, r2, r3;
            ldmx4(aA, r0, r1, r2, r3);
            int d0 = 0, d1 = 0, d2 = 0, d3 = 0;
            mma_s8(d0, d1, d2, d3, A0[0][0], A0[0][1], A0[0][2], A0[0][3], r0, r1);
            mma_s8(d0, d1, d2, d3, A0[1][0], A0[1][1], A0[1][2], A0[1][3], r2, r3);
            const int nl = sub * 8 + 2 * tm4;
            float x20 = x2s[nl], x21 = x2s[nl + 1];
            float cc0 = sxs[nl] * QS, cc1 = sxs[nl + 1] * QS;
            best0 = fminf(best0, fmaxf(fmaf((float)d0, cc0, x20) + p2a, 0.0f));
            best0 = fminf(best0, fmaxf(fmaf((float)d1, cc1, x21) + p2a, 0.0f));
            best1 = fminf(best1, fmaxf(fmaf((float)d2, cc0, x20) + p2b, 0.0f));
            best1 = fminf(best1, fmaxf(fmaf((float)d3, cc1, x21) + p2b, 0.0f));
        }
        best0 = fminf(best0, __shfl_xor_sync(0xFFFFFFFFu, best0, 1));
        best0 = fminf(best0, __shfl_xor_sync(0xFFFFFFFFu, best0, 2));
        best1 = fminf(best1, __shfl_xor_sync(0xFFFFFFFFu, best1, 1));
        best1 = fminf(best1, __shfl_xor_sync(0xFFFFFFFFu, best1, 2));
    }

    if (tm4 == 0) {
        atomicMin(&g_thr[bp0], __float_as_uint(best0));
        atomicMin(&g_thr[bp1], __float_as_uint(best1));
    }

    float thr0 = best0 + MARGIN;
    float thr1 = best1 + MARGIN;
    float thr0m = thr0 - p2a;
    float thr1m = thr1 - p2b;
    __syncthreads();            /* prepass reads done before restaging buf0 */

    stage(0);

    for (int it = 0; it < NCHUNK; it++) {
        float gt0 = __uint_as_float(__ldcg((const unsigned*)&g_thr[bp0]));
        float gt1 = __uint_as_float(__ldcg((const unsigned*)&g_thr[bp1]));

        if (it + 1 < NCHUNK) {
            stage(it + 1);
            asm volatile("cp.async.wait_group 1;");
        } else {
            asm volatile("cp.async.wait_group 0;");
        }
        best0 = fminf(best0, gt0);
        best1 = fminf(best1, gt1);
        thr0 = best0 + MARGIN; thr0m = thr0 - p2a;
        thr1 = best1 + MARGIN; thr1m = thr1 - p2b;
        __syncthreads();

        const uint32_t sb = sbase + (it & 1) * BUFB;
        const float* x2s = (const float*)(sbuf + X2OFF + (it & 1) * 256);
        const float* sxs = (const float*)(sbuf + SXOFF + (it & 1) * 256);

        #pragma unroll 1
        for (int s2 = 0; s2 < 4; s2++) {
            const int sa = s2 * 2, sbn = s2 * 2 + 1;
            uint32_t aA = sb + (uint32_t)(sa * 8) * PITCHB + lrow;
            uint32_t aB = sb + (uint32_t)(sbn * 8) * PITCHB + lrow;
            uint32_t ra0, ra1, ra2, ra3, rb0, rb1, rb2, rb3;
            ldmx4(aA, ra0, ra1, ra2, ra3);
            ldmx4(aB, rb0, rb1, rb2, rb3);

            int dA0 = 0, dA1 = 0, dA2 = 0, dA3 = 0;
            int dB0 = 0, dB1 = 0, dB2 = 0, dB3 = 0;
            mma_s8(dA0, dA1, dA2, dA3, A0[0][0], A0[0][1], A0[0][2], A0[0][3], ra0, ra1);
            mma_s8(dB0, dB1, dB2, dB3, A0[0][0], A0[0][1], A0[0][2], A0[0][3], rb0, rb1);
            mma_s8(dA0, dA1, dA2, dA3, A0[1][0], A0[1][1], A0[1][2], A0[1][3], ra2, ra3);
            mma_s8(dB0, dB1, dB2, dB3, A0[1][0], A0[1][1], A0[1][2], A0[1][3], rb2, rb3);

            #pragma unroll
            for (int half = 0; half < 2; half++) {
                const int sub = half ? sbn : sa;
                int d0 = half ? dB0 : dA0, d1 = half ? dB1 : dA1;
                int d2 = half ? dB2 : dA2, d3 = half ? dB3 : dA3;
                const int nl = sub * 8 + 2 * tm4;
                float x20 = x2s[nl];
                float x21 = x2s[nl + 1];
                float cc0 = sxs[nl] * QS;
                float cc1 = sxs[nl + 1] * QS;
                float t0 = fmaf((float)d0, cc0, x20);
                float t1 = fmaf((float)d1, cc1, x21);
                float t2 = fmaf((float)d2, cc0, x20);
                float t3 = fmaf((float)d3, cc1, x21);
                if (fminf(t0, t1) < thr0m || fminf(t2, t3) < thr1m) {
                    const int nglob = n0 + it * CHN + nl;
                    float s00 = fmaxf(t0 + p2a, 0.0f);
                    float s01 = fmaxf(t1 + p2a, 0.0f);
                    float s10 = fmaxf(t2 + p2b, 0.0f);
                    float s11 = fmaxf(t3 + p2b, 0.0f);
                    if (s00 < thr0) {
                        if (s00 < best0) {
                            best0 = s00; thr0 = s00 + MARGIN; thr0m = thr0 - p2a;
                            atomicMin(&g_thr[bp0], __float_as_uint(best0));
                        }
                        int sl = atomicAdd(&g_cnt[bp0], 1);
                        if (sl < CAP) g_cand[bp0 * CAP + sl] = nglob;
                    }
                    if (s01 < thr0) {
                        if (s01 < best0) {
                            best0 = s01; thr0 = s01 + MARGIN; thr0m = thr0 - p2a;
                            atomicMin(&g_thr[bp0], __float_as_uint(best0));
                        }
                        int sl = atomicAdd(&g_cnt[bp0], 1);
                        if (sl < CAP) g_cand[bp0 * CAP + sl] = nglob + 1;
                    }
                    if (s10 < thr1) {
                        if (s10 < best1) {
                            best1 = s10; thr1 = s10 + MARGIN; thr1m = thr1 - p2b;
                            atomicMin(&g_thr[bp1], __float_as_uint(best1));
                        }
                        int sl = atomicAdd(&g_cnt[bp1], 1);
                        if (sl < CAP) g_cand[bp1 * CAP + sl] = nglob;
                    }
                    if (s11 < thr1) {
                        if (s11 < best1) {
                            best1 = s11; thr1 = s11 + MARGIN; thr1m = thr1 - p2b;
                            atomicMin(&g_thr[bp1], __float_as_uint(best1));
                        }
                        int sl = atomicAdd(&g_cnt[bp1], 1);
                        if (sl < CAP) g_cand[bp1 * CAP + sl] = nglob + 1;
                    }
                }
            }
        }
        __syncthreads();
    }
}

/* ------------------------------------------------------------------ */
/* refine: warp per (b,p); lane-per-candidate exact fp32 recompute. */
__global__ void refine_kernel(const float* __restrict__ x, float* __restrict__ out) {
    __shared__ float ps[8][DD];
    const int wid = threadIdx.x >> 5;
    const int lane = threadIdx.x & 31;
    const int pair = blockIdx.x * 8 + wid;
    const int bb = pair / PP, p = pair % PP;

    ((float2*)ps[wid])[lane] = ((const float2*)(g_pn + (size_t)p * DD))[lane];
    __syncwarp();
    const float p2 = g_p2[p];
    int cnt = g_cnt[pair];
    if (cnt > CAP) cnt = CAP;

    unsigned long long bestk = 0xFFFFFFFFFFFFFFFFull;
    for (int base = 0; base < cnt; base += 32) {
        int i = base + lane;
        if (i < cnt) {
            int n = g_cand[pair * CAP + i];
            const float4* xr = (const float4*)(x + ((size_t)bb * NN + n) * DD);
            float dot = 0.0f, x2 = 0.0f;
            #pragma unroll
            for (int c = 0; c < 16; c++) {
                float4 xv = __ldg(xr + c);
                float4 pv = ((const float4*)ps[wid])[c];
                dot = fmaf(xv.x, pv.x, dot); dot = fmaf(xv.y, pv.y, dot);
                dot = fmaf(xv.z, pv.z, dot); dot = fmaf(xv.w, pv.w, dot);
                x2 = fmaf(xv.x, xv.x, x2); x2 = fmaf(xv.y, xv.y, x2);
                x2 = fmaf(xv.z, xv.z, x2); x2 = fmaf(xv.w, xv.w, x2);
            }
            float sq = fmaxf(x2 - 2.0f * dot + p2, 0.0f);
            unsigned long long key =
                ((unsigned long long)__float_as_uint(sq) << 32) | (unsigned)n;
            if (key < bestk) bestk = key;
        }
    }
    #pragma unroll
    for (int o = 16; o; o >>= 1) {
        unsigned long long ok = __shfl_xor_sync(0xFFFFFFFFu, bestk, o);
        if (ok < bestk) bestk = ok;
    }
    if (lane == 0) {
        float sq = __uint_as_float((unsigned)(bestk >> 32));
        out[pair] = sqrtf(sq + 1e-8f);
        out[BB * PP + pair] = (float)(unsigned)(bestk & 0xFFFFFFFFu);
    }
}

extern "C" void kernel_launch(void* const* d_in, const int* in_sizes, int n_in,
                              void* d_out, int out_size) {
    const float* x = (const float*)d_in[0];
    const float* proto = (const float*)d_in[1];
    float* out = (float*)d_out;

    prep_conv_kernel<<<64 + (BB * NN) / 32, 256>>>(proto, x);
    dim3 grid(NSPLIT, PP / PT, BB);
    main_kernel<<<grid, 256>>>();
    refine_kernel<<<(BB * PP) / 8, 256>>>(x, out);
}

// round 16
// speedup vs baseline: 2.0971x; 1.8726x over previous
#include <cuda_runtime.h>
#include <cuda_fp16.h>
#include <math.h>
#include <stdint.h>

#define BB 8
#define NN 16384
#define PP 512
#define DD 64
#define PT 128                  /* p per CTA (8 warps x 16) */
#define NSPLIT 16
#define NPER (NN / NSPLIT)      /* 1024 */
#define CHN 64                  /* n per chunk */
#define NCHUNK (NPER / CHN)     /* 16 */
#define PITCHB 144              /* bytes per n-row in smem (128 data + 16 pad) */
#define BUFB (CHN * PITCHB)     /* 9216 bytes per buffer */
#define X2OFF (2 * BUFB)        /* x2 buffers after the two data buffers */
#define MARGIN 0.125f           /* >= 2*eps safety for fp16 1-term approx */
#define CAP 512
#define SSTRIDE (NN / 64)       /* 256: global sample stride for prepass */

__device__ unsigned g_ph[PP * DD / 2];     /* fp16x2 normalized protos [p][d] */
__device__ float g_pn[PP * DD];            /* fp32 normalized protos */
__device__ float g_p2[PP];
__device__ unsigned g_xh[BB * NN * DD / 2];/* fp16x2 x, [b][n][d] */
__device__ float g_x2[BB * NN];
__device__ unsigned g_thr[BB * PP];        /* shared best sq (float bits) */
__device__ int g_cnt[BB * PP];
__device__ int g_cand[BB * PP * CAP];

__device__ __forceinline__ void mma_f16(float& d0, float& d1, float& d2, float& d3,
                                        uint32_t a0, uint32_t a1, uint32_t a2, uint32_t a3,
                                        uint32_t b0, uint32_t b1) {
    asm("mma.sync.aligned.m16n8k16.row.col.f32.f16.f16.f32 "
        "{%0,%1,%2,%3}, {%4,%5,%6,%7}, {%8,%9}, {%0,%1,%2,%3};"
        : "+f"(d0), "+f"(d1), "+f"(d2), "+f"(d3)
        : "r"(a0), "r"(a1), "r"(a2), "r"(a3), "r"(b0), "r"(b1));
}
__device__ __forceinline__ void ldmx4(uint32_t a, uint32_t& r0, uint32_t& r1,
                                      uint32_t& r2, uint32_t& r3) {
    asm volatile("ldmatrix.sync.aligned.m8n8.x4.shared.b16 {%0,%1,%2,%3}, [%4];"
                 : "=r"(r0), "=r"(r1), "=r"(r2), "=r"(r3) : "r"(a));
}
__device__ __forceinline__ void cpa16(uint32_t s, const void* g) {
    asm volatile("cp.async.cg.shared.global [%0], [%1], 16;" :: "r"(s), "l"(g));
}
__device__ __forceinline__ uint32_t smem_u32(const void* p) {
    uint32_t a;
    asm("{ .reg .u64 t; cvta.to.shared.u64 t, %1; cvt.u32.u64 %0, t; }"
        : "=r"(a) : "l"(p));
    return a;
}

/* ------------------------------------------------------------------ */
/* fused prep (blocks 0..63) + conv (blocks 64.., 8 rows per warp).   */
__global__ void prep_conv_kernel(const float* __restrict__ proto,
                                 const float* __restrict__ x) {
    if (blockIdx.x < 64) {
        int t = blockIdx.x * blockDim.x + threadIdx.x;
        if (t < BB * PP) { g_cnt[t] = 0; g_thr[t] = 0x7f800000u; }

        int gw = t >> 5, lane = t & 31;
        if (gw >= PP) return;
        float2 v = ((const float2*)(proto + gw * DD))[lane];
        float s = v.x * v.x + v.y * v.y;
        #pragma unroll
        for (int o = 16; o; o >>= 1) s += __shfl_xor_sync(0xFFFFFFFFu, s, o);
        float inv = 1.0f / fmaxf(sqrtf(s), 1e-12f);
        float a = v.x * inv, b = v.y * inv;

        __half2 h = __floats2half2_rn(a, b);
        g_ph[gw * 32 + lane] = *(const unsigned*)&h;
        g_pn[gw * DD + 2 * lane + 0] = a;
        g_pn[gw * DD + 2 * lane + 1] = b;

        float q = a * a + b * b;
        #pragma unroll
        for (int o = 16; o; o >>= 1) q += __shfl_xor_sync(0xFFFFFFFFu, q, o);
        if (lane == 0) g_p2[gw] = q;
    } else {
        /* conv: each warp converts 8 rows (MLP=8) */
        const int lane = threadIdx.x & 31;
        const int row0 = ((int)(blockIdx.x - 64) * 8 + (threadIdx.x >> 5)) * 8;
        if (row0 >= BB * NN) return;

        float2 v[8];
        #pragma unroll
        for (int r = 0; r < 8; r++)
            v[r] = ((const float2*)(x + (size_t)(row0 + r) * DD))[lane];

        float s[8];
        #pragma unroll
        for (int r = 0; r < 8; r++) {
            __half2 h = __floats2half2_rn(v[r].x, v[r].y);
            g_xh[(size_t)(row0 + r) * 32 + lane] = *(const unsigned*)&h;
            s[r] = fmaf(v[r].x, v[r].x, v[r].y * v[r].y);
        }
        #pragma unroll
        for (int o = 16; o; o >>= 1) {
            #pragma unroll
            for (int r = 0; r < 8; r++)
                s[r] += __shfl_xor_sync(0xFFFFFFFFu, s[r], o);
        }
        if (lane < 8) g_x2[row0 + lane] = s[lane];
    }
}

/* ------------------------------------------------------------------ */
/* main: fp16 1-term GEMM, cp.async double buffer, 2x MMA ILP.
   64-sample strided prepass + chip-wide shared thresholds (g_thr),
   then conservative proxy-filtered candidate collection.              */
__global__ void __launch_bounds__(256, 4)
main_kernel() {
    __shared__ __align__(16) unsigned char sbuf[2 * BUFB + 2 * 256];
    const uint32_t sbase = smem_u32(sbuf);

    const int tid = threadIdx.x;
    const int w = tid >> 5, lane = tid & 31;
    const int g = lane >> 2, tm4 = lane & 3;
    const int bb = blockIdx.z;
    const int p0 = blockIdx.y * PT + w * 16;
    const int n0 = blockIdx.x * NPER;

    uint32_t A0[4][4];
    {
        const unsigned* h0 = g_ph + (size_t)p0 * 32;
        #pragma unroll
        for (int k8 = 0; k8 < 4; k8++) {
            int c = k8 * 8 + tm4;
            A0[k8][0] = __ldg(h0 + (size_t)g * 32 + c);
            A0[k8][1] = __ldg(h0 + (size_t)(g + 8) * 32 + c);
            A0[k8][2] = __ldg(h0 + (size_t)g * 32 + c + 4);
            A0[k8][3] = __ldg(h0 + (size_t)(g + 8) * 32 + c + 4);
        }
    }
    const float p2a = g_p2[p0 + g];
    const float p2b = g_p2[p0 + g + 8];
    const int bp0 = bb * PP + p0 + g;
    const int bp1 = bp0 + 8;

    const unsigned char* xhB = (const unsigned char*)g_xh +
                               (size_t)bb * NN * (DD * 2);
    const unsigned char* xh = xhB + (size_t)n0 * (DD * 2);
    const float* x2B = g_x2 + (size_t)bb * NN;
    const unsigned char* x2g = (const unsigned char*)(x2B + n0);

    const uint32_t lrow = (uint32_t)(lane & 7) * PITCHB + (uint32_t)(lane >> 3) * 16;

    auto stage = [&](int it) {
        const uint32_t sb = sbase + (it & 1) * BUFB;
        const unsigned char* gsrc = xh + (size_t)it * (CHN * DD * 2);
        #pragma unroll
        for (int k = 0; k < 2; k++) {
            int idx = tid + k * 256;
            cpa16(sb + (uint32_t)(idx >> 3) * PITCHB + (uint32_t)(idx & 7) * 16,
                  gsrc + (size_t)idx * 16);
        }
        if (tid < 16)
            cpa16(sbase + X2OFF + (it & 1) * 256 + tid * 16,
                  x2g + (size_t)it * 256 + tid * 16);
        asm volatile("cp.async.commit_group;");
    };

    /* ---- prepass: 64 rows strided across ALL of N ---- */
    {
        #pragma unroll
        for (int k = 0; k < 2; k++) {
            int idx = tid + k * 256;
            int row = idx >> 3, seg = idx & 7;
            cpa16(sbase + (uint32_t)row * PITCHB + (uint32_t)seg * 16,
                  xhB + (size_t)row * SSTRIDE * (DD * 2) + seg * 16);
        }
        if (tid < 64)
            ((float*)(sbuf + X2OFF))[tid] = x2B[(size_t)tid * SSTRIDE];
        asm volatile("cp.async.commit_group;");
        asm volatile("cp.async.wait_group 0;");
        __syncthreads();
    }

    float best0 = __int_as_float(0x7f800000);
    float best1 = __int_as_float(0x7f800000);
    {
        const float* x2s = (const float*)(sbuf + X2OFF);
        #pragma unroll
        for (int sub = 0; sub < 8; sub++) {
            uint32_t aA = sbase + (uint32_t)(sub * 8) * PITCHB + lrow;
            uint32_t a00, a01, a10, a11, a20, a21, a30, a31;
            ldmx4(aA,      a00, a01, a10, a11);
            ldmx4(aA + 64, a20, a21, a30, a31);
            float d0 = 0.f, d1 = 0.f, d2 = 0.f, d3 = 0.f;
            mma_f16(d0, d1, d2, d3, A0[0][0], A0[0][1], A0[0][2], A0[0][3], a00, a01);
            mma_f16(d0, d1, d2, d3, A0[1][0], A0[1][1], A0[1][2], A0[1][3], a10, a11);
            mma_f16(d0, d1, d2, d3, A0[2][0], A0[2][1], A0[2][2], A0[2][3], a20, a21);
            mma_f16(d0, d1, d2, d3, A0[3][0], A0[3][1], A0[3][2], A0[3][3], a30, a31);
            const int nl = sub * 8 + 2 * tm4;
            float x20 = x2s[nl], x21 = x2s[nl + 1];
            best0 = fminf(best0, fmaxf(fmaf(d0, -2.0f, x20) + p2a, 0.0f));
            best0 = fminf(best0, fmaxf(fmaf(d1, -2.0f, x21) + p2a, 0.0f));
            best1 = fminf(best1, fmaxf(fmaf(d2, -2.0f, x20) + p2b, 0.0f));
            best1 = fminf(best1, fmaxf(fmaf(d3, -2.0f, x21) + p2b, 0.0f));
        }
        best0 = fminf(best0, __shfl_xor_sync(0xFFFFFFFFu, best0, 1));
        best0 = fminf(best0, __shfl_xor_sync(0xFFFFFFFFu, best0, 2));
        best1 = fminf(best1, __shfl_xor_sync(0xFFFFFFFFu, best1, 1));
        best1 = fminf(best1, __shfl_xor_sync(0xFFFFFFFFu, best1, 2));
    }

    /* publish prepass seed (1 lane per p-row group) */
    if (tm4 == 0) {
        atomicMin(&g_thr[bp0], __float_as_uint(best0));
        atomicMin(&g_thr[bp1], __float_as_uint(best1));
    }

    float thr0 = best0 + MARGIN;
    float thr1 = best1 + MARGIN;
    float thr0m = thr0 - p2a;
    float thr1m = thr1 - p2b;
    __syncthreads();            /* prepass reads done before restaging buf0 */

    stage(0);

    for (int it = 0; it < NCHUNK; it++) {
        /* fold in chip-wide best thresholds (independent loads, hoisted) */
        float gt0 = __uint_as_float(__ldcg((const unsigned*)&g_thr[bp0]));
        float gt1 = __uint_as_float(__ldcg((const unsigned*)&g_thr[bp1]));

        if (it + 1 < NCHUNK) {
            stage(it + 1);
            asm volatile("cp.async.wait_group 1;");
        } else {
            asm volatile("cp.async.wait_group 0;");
        }
        best0 = fminf(best0, gt0);
        best1 = fminf(best1, gt1);
        thr0 = best0 + MARGIN; thr0m = thr0 - p2a;
        thr1 = best1 + MARGIN; thr1m = thr1 - p2b;
        __syncthreads();

        const uint32_t sb = sbase + (it & 1) * BUFB;
        const float* x2s = (const float*)(sbuf + X2OFF + (it & 1) * 256);

        #pragma unroll 1
        for (int s2 = 0; s2 < 4; s2++) {
            const int sa = s2 * 2, sbn = s2 * 2 + 1;
            uint32_t aA = sb + (uint32_t)(sa * 8) * PITCHB + lrow;
            uint32_t aB = sb + (uint32_t)(sbn * 8) * PITCHB + lrow;
            uint32_t a00, a01, a10, a11, a20, a21, a30, a31;
            uint32_t b00, b01, b10, b11, b20, b21, b30, b31;
            ldmx4(aA,      a00, a01, a10, a11);
            ldmx4(aA + 64, a20, a21, a30, a31);
            ldmx4(aB,      b00, b01, b10, b11);
            ldmx4(aB + 64, b20, b21, b30, b31);

            float dA0 = 0.f, dA1 = 0.f, dA2 = 0.f, dA3 = 0.f;
            float dB0 = 0.f, dB1 = 0.f, dB2 = 0.f, dB3 = 0.f;
            mma_f16(dA0, dA1, dA2, dA3, A0[0][0], A0[0][1], A0[0][2], A0[0][3], a00, a01);
            mma_f16(dB0, dB1, dB2, dB3, A0[0][0], A0[0][1], A0[0][2], A0[0][3], b00, b01);
            mma_f16(dA0, dA1, dA2, dA3, A0[1][0], A0[1][1], A0[1][2], A0[1][3], a10, a11);
            mma_f16(dB0, dB1, dB2, dB3, A0[1][0], A0[1][1], A0[1][2], A0[1][3], b10, b11);
            mma_f16(dA0, dA1, dA2, dA3, A0[2][0], A0[2][1], A0[2][2], A0[2][3], a20, a21);
            mma_f16(dB0, dB1, dB2, dB3, A0[2][0], A0[2][1], A0[2][2], A0[2][3], b20, b21);
            mma_f16(dA0, dA1, dA2, dA3, A0[3][0], A0[3][1], A0[3][2], A0[3][3], a30, a31);
            mma_f16(dB0, dB1, dB2, dB3, A0[3][0], A0[3][1], A0[3][2], A0[3][3], b30, b31);

            #pragma unroll
            for (int half = 0; half < 2; half++) {
                const int sub = half ? sbn : sa;
                float d0 = half ? dB0 : dA0, d1 = half ? dB1 : dA1;
                float d2 = half ? dB2 : dA2, d3 = half ? dB3 : dA3;
                const int nl = sub * 8 + 2 * tm4;
                float x20 = x2s[nl];
                float x21 = x2s[nl + 1];
                float t0 = fmaf(d0, -2.0f, x20);
                float t1 = fmaf(d1, -2.0f, x21);
                float t2 = fmaf(d2, -2.0f, x20);
                float t3 = fmaf(d3, -2.0f, x21);
                if (fminf(t0, t1) < thr0m || fminf(t2, t3) < thr1m) {
                    const int nglob = n0 + it * CHN + nl;
                    float s00 = fmaxf(t0 + p2a, 0.0f);
                    float s01 = fmaxf(t1 + p2a, 0.0f);
                    float s10 = fmaxf(t2 + p2b, 0.0f);
                    float s11 = fmaxf(t3 + p2b, 0.0f);
                    if (s00 < thr0) {
                        if (s00 < best0) {
                            best0 = s00; thr0 = s00 + MARGIN; thr0m = thr0 - p2a;
                            atomicMin(&g_thr[bp0], __float_as_uint(best0));
                        }
                        int sl = atomicAdd(&g_cnt[bp0], 1);
                        if (sl < CAP) g_cand[bp0 * CAP + sl] = nglob;
                    }
                    if (s01 < thr0) {
                        if (s01 < best0) {
                            best0 = s01; thr0 = s01 + MARGIN; thr0m = thr0 - p2a;
                            atomicMin(&g_thr[bp0], __float_as_uint(best0));
                        }
                        int sl = atomicAdd(&g_cnt[bp0], 1);
                        if (sl < CAP) g_cand[bp0 * CAP + sl] = nglob + 1;
                    }
                    if (s10 < thr1) {
                        if (s10 < best1) {
                            best1 = s10; thr1 = s10 + MARGIN; thr1m = thr1 - p2b;
                            atomicMin(&g_thr[bp1], __float_as_uint(best1));
                        }
                        int sl = atomicAdd(&g_cnt[bp1], 1);
                        if (sl < CAP) g_cand[bp1 * CAP + sl] = nglob;
                    }
                    if (s11 < thr1) {
                        if (s11 < best1) {
                            best1 = s11; thr1 = s11 + MARGIN; thr1m = thr1 - p2b;
                            atomicMin(&g_thr[bp1], __float_as_uint(best1));
                        }
                        int sl = atomicAdd(&g_cnt[bp1], 1);
                        if (sl < CAP) g_cand[bp1 * CAP + sl] = nglob + 1;
                    }
                }
            }
        }
        __syncthreads();
    }
}

/* ------------------------------------------------------------------ */
/* refine: warp per (b,p); lane-per-candidate exact fp32 recompute. */
__global__ void refine_kernel(const float* __restrict__ x, float* __restrict__ out) {
    __shared__ float ps[8][DD];
    const int wid = threadIdx.x >> 5;
    const int lane = threadIdx.x & 31;
    const int pair = blockIdx.x * 8 + wid;
    const int bb = pair / PP, p = pair % PP;

    ((float2*)ps[wid])[lane] = ((const float2*)(g_pn + (size_t)p * DD))[lane];
    __syncwarp();
    const float p2 = g_p2[p];
    int cnt = g_cnt[pair];
    if (cnt > CAP) cnt = CAP;

    unsigned long long bestk = 0xFFFFFFFFFFFFFFFFull;
    for (int base = 0; base < cnt; base += 32) {
        int i = base + lane;
        if (i < cnt) {
            int n = g_cand[pair * CAP + i];
            const float4* xr = (const float4*)(x + ((size_t)bb * NN + n) * DD);
            float dot = 0.0f, x2 = 0.0f;
            #pragma unroll
            for (int c = 0; c < 16; c++) {
                float4 xv = __ldg(xr + c);
                float4 pv = ((const float4*)ps[wid])[c];
                dot = fmaf(xv.x, pv.x, dot); dot = fmaf(xv.y, pv.y, dot);
                dot = fmaf(xv.z, pv.z, dot); dot = fmaf(xv.w, pv.w, dot);
                x2 = fmaf(xv.x, xv.x, x2); x2 = fmaf(xv.y, xv.y, x2);
                x2 = fmaf(xv.z, xv.z, x2); x2 = fmaf(xv.w, xv.w, x2);
            }
            float sq = fmaxf(x2 - 2.0f * dot + p2, 0.0f);
            unsigned long long key =
                ((unsigned long long)__float_as_uint(sq) << 32) | (unsigned)n;
            if (key < bestk) bestk = key;
        }
    }
    #pragma unroll
    for (int o = 16; o; o >>= 1) {
        unsigned long long ok = __shfl_xor_sync(0xFFFFFFFFu, bestk, o);
        if (ok < bestk) bestk = ok;
    }
    if (lane == 0) {
        float sq = __uint_as_float((unsigned)(bestk >> 32));
        out[pair] = sqrtf(sq + 1e-8f);
        out[BB * PP + pair] = (float)(unsigned)(bestk & 0xFFFFFFFFu);
    }
}

extern "C" void kernel_launch(void* const* d_in, const int* in_sizes, int n_in,
                              void* d_out, int out_size) {
    const float* x = (const float*)d_in[0];
    const float* proto = (const float*)d_in[1];
    float* out = (float*)d_out;

    prep_conv_kernel<<<64 + (BB * NN) / 64, 256>>>(proto, x);
    dim3 grid(NSPLIT, PP / PT, BB);
    main_kernel<<<grid, 256>>>();
    refine_kernel<<<(BB * PP) / 8, 256>>>(x, out);
}

// round 17
// speedup vs baseline: 2.1449x; 1.0228x over previous
#include <cuda_runtime.h>
#include <cuda_fp16.h>
#include <math.h>
#include <stdint.h>

#define BB 8
#define NN 16384
#define PP 512
#define DD 64
#define PT 64                   /* p per CTA (4 warps x 16) */
#define NSPLIT 16
#define NPER (NN / NSPLIT)      /* 1024 */
#define CHN 64                  /* n per chunk */
#define NCHUNK (NPER / CHN)     /* 16 */
#define PITCHB 144              /* bytes per n-row in smem (128 data + 16 pad) */
#define BUFB (CHN * PITCHB)     /* 9216 bytes per buffer */
#define X2OFF (2 * BUFB)        /* x2 buffers after the two data buffers */
#define MARGIN 0.125f           /* >= 2*eps safety for fp16 1-term approx */
#define CAP 512
#define SSTRIDE (NN / 64)       /* 256: global sample stride for prepass */

__device__ unsigned g_ph[PP * DD / 2];     /* fp16x2 normalized protos [p][d] */
__device__ float g_pn[PP * DD];            /* fp32 normalized protos */
__device__ float g_p2[PP];
__device__ unsigned g_xh[BB * NN * DD / 2];/* fp16x2 x, [b][n][d] */
__device__ float g_x2[BB * NN];
__device__ unsigned g_thr[BB * PP];        /* shared best sq (float bits) */
__device__ int g_cnt[BB * PP];
__device__ int g_cand[BB * PP * CAP];

__device__ __forceinline__ void mma_f16(float& d0, float& d1, float& d2, float& d3,
                                        uint32_t a0, uint32_t a1, uint32_t a2, uint32_t a3,
                                        uint32_t b0, uint32_t b1) {
    asm("mma.sync.aligned.m16n8k16.row.col.f32.f16.f16.f32 "
        "{%0,%1,%2,%3}, {%4,%5,%6,%7}, {%8,%9}, {%0,%1,%2,%3};"
        : "+f"(d0), "+f"(d1), "+f"(d2), "+f"(d3)
        : "r"(a0), "r"(a1), "r"(a2), "r"(a3), "r"(b0), "r"(b1));
}
__device__ __forceinline__ void ldmx4(uint32_t a, uint32_t& r0, uint32_t& r1,
                                      uint32_t& r2, uint32_t& r3) {
    asm volatile("ldmatrix.sync.aligned.m8n8.x4.shared.b16 {%0,%1,%2,%3}, [%4];"
                 : "=r"(r0), "=r"(r1), "=r"(r2), "=r"(r3) : "r"(a));
}
__device__ __forceinline__ void cpa16(uint32_t s, const void* g) {
    asm volatile("cp.async.cg.shared.global [%0], [%1], 16;" :: "r"(s), "l"(g));
}
__device__ __forceinline__ uint32_t smem_u32(const void* p) {
    uint32_t a;
    asm("{ .reg .u64 t; cvta.to.shared.u64 t, %1; cvt.u32.u64 %0, t; }"
        : "=r"(a) : "l"(p));
    return a;
}

/* ------------------------------------------------------------------ */
/* fused prep (blocks 0..63) + conv (blocks 64.., 4 rows per warp).   */
__global__ void prep_conv_kernel(const float* __restrict__ proto,
                                 const float* __restrict__ x) {
    if (blockIdx.x < 64) {
        int t = blockIdx.x * blockDim.x + threadIdx.x;
        if (t < BB * PP) { g_cnt[t] = 0; g_thr[t] = 0x7f800000u; }

        int gw = t >> 5, lane = t & 31;
        if (gw >= PP) return;
        float2 v = ((const float2*)(proto + gw * DD))[lane];
        float s = v.x * v.x + v.y * v.y;
        #pragma unroll
        for (int o = 16; o; o >>= 1) s += __shfl_xor_sync(0xFFFFFFFFu, s, o);
        float inv = 1.0f / fmaxf(sqrtf(s), 1e-12f);
        float a = v.x * inv, b = v.y * inv;

        __half2 h = __floats2half2_rn(a, b);
        g_ph[gw * 32 + lane] = *(const unsigned*)&h;
        g_pn[gw * DD + 2 * lane + 0] = a;
        g_pn[gw * DD + 2 * lane + 1] = b;

        float q = a * a + b * b;
        #pragma unroll
        for (int o = 16; o; o >>= 1) q += __shfl_xor_sync(0xFFFFFFFFu, q, o);
        if (lane == 0) g_p2[gw] = q;
    } else {
        /* conv: each warp converts 4 rows (MLP=4, measured-best) */
        const int lane = threadIdx.x & 31;
        const int row0 = ((int)(blockIdx.x - 64) * 8 + (threadIdx.x >> 5)) * 4;
        if (row0 >= BB * NN) return;

        float2 v[4];
        #pragma unroll
        for (int r = 0; r < 4; r++)
            v[r] = ((const float2*)(x + (size_t)(row0 + r) * DD))[lane];

        float s[4];
        #pragma unroll
        for (int r = 0; r < 4; r++) {
            __half2 h = __floats2half2_rn(v[r].x, v[r].y);
            g_xh[(size_t)(row0 + r) * 32 + lane] = *(const unsigned*)&h;
            s[r] = fmaf(v[r].x, v[r].x, v[r].y * v[r].y);
        }
        #pragma unroll
        for (int o = 16; o; o >>= 1) {
            #pragma unroll
            for (int r = 0; r < 4; r++)
                s[r] += __shfl_xor_sync(0xFFFFFFFFu, s[r], o);
        }
        if (lane < 4) g_x2[row0 + lane] = s[lane];
    }
}

/* ------------------------------------------------------------------ */
/* main: fp16 1-term GEMM, cp.async double buffer, 2x MMA ILP.
   128-thread CTA (4 warps, 64 p), occupancy 8 -> ~1% SM imbalance.
   64-sample strided prepass + chip-wide shared thresholds (g_thr),
   then conservative proxy-filtered candidate collection.              */
__global__ void __launch_bounds__(128, 8)
main_kernel() {
    __shared__ __align__(16) unsigned char sbuf[2 * BUFB + 2 * 256];
    const uint32_t sbase = smem_u32(sbuf);

    const int tid = threadIdx.x;
    const int w = tid >> 5, lane = tid & 31;
    const int g = lane >> 2, tm4 = lane & 3;
    const int bb = blockIdx.z;
    const int p0 = blockIdx.y * PT + w * 16;
    const int n0 = blockIdx.x * NPER;

    uint32_t A0[4][4];
    {
        const unsigned* h0 = g_ph + (size_t)p0 * 32;
        #pragma unroll
        for (int k8 = 0; k8 < 4; k8++) {
            int c = k8 * 8 + tm4;
            A0[k8][0] = __ldg(h0 + (size_t)g * 32 + c);
            A0[k8][1] = __ldg(h0 + (size_t)(g + 8) * 32 + c);
            A0[k8][2] = __ldg(h0 + (size_t)g * 32 + c + 4);
            A0[k8][3] = __ldg(h0 + (size_t)(g + 8) * 32 + c + 4);
        }
    }
    const float p2a = g_p2[p0 + g];
    const float p2b = g_p2[p0 + g + 8];
    const int bp0 = bb * PP + p0 + g;
    const int bp1 = bp0 + 8;

    const unsigned char* xhB = (const unsigned char*)g_xh +
                               (size_t)bb * NN * (DD * 2);
    const unsigned char* xh = xhB + (size_t)n0 * (DD * 2);
    const float* x2B = g_x2 + (size_t)bb * NN;
    const unsigned char* x2g = (const unsigned char*)(x2B + n0);

    const uint32_t lrow = (uint32_t)(lane & 7) * PITCHB + (uint32_t)(lane >> 3) * 16;

    auto stage = [&](int it) {
        const uint32_t sb = sbase + (it & 1) * BUFB;
        const unsigned char* gsrc = xh + (size_t)it * (CHN * DD * 2);
        #pragma unroll
        for (int k = 0; k < 4; k++) {
            int idx = tid + k * 128;
            cpa16(sb + (uint32_t)(idx >> 3) * PITCHB + (uint32_t)(idx & 7) * 16,
                  gsrc + (size_t)idx * 16);
        }
        if (tid < 16)
            cpa16(sbase + X2OFF + (it & 1) * 256 + tid * 16,
                  x2g + (size_t)it * 256 + tid * 16);
        asm volatile("cp.async.commit_group;");
    };

    /* ---- prepass: 64 rows strided across ALL of N ---- */
    {
        #pragma unroll
        for (int k = 0; k < 4; k++) {
            int idx = tid + k * 128;
            int row = idx >> 3, seg = idx & 7;
            cpa16(sbase + (uint32_t)row * PITCHB + (uint32_t)seg * 16,
                  xhB + (size_t)row * SSTRIDE * (DD * 2) + seg * 16);
        }
        if (tid < 64)
            ((float*)(sbuf + X2OFF))[tid] = x2B[(size_t)tid * SSTRIDE];
        asm volatile("cp.async.commit_group;");
        asm volatile("cp.async.wait_group 0;");
        __syncthreads();
    }

    float best0 = __int_as_float(0x7f800000);
    float best1 = __int_as_float(0x7f800000);
    {
        const float* x2s = (const float*)(sbuf + X2OFF);
        #pragma unroll
        for (int sub = 0; sub < 8; sub++) {
            uint32_t aA = sbase + (uint32_t)(sub * 8) * PITCHB + lrow;
            uint32_t a00, a01, a10, a11, a20, a21, a30, a31;
            ldmx4(aA,      a00, a01, a10, a11);
            ldmx4(aA + 64, a20, a21, a30, a31);
            float d0 = 0.f, d1 = 0.f, d2 = 0.f, d3 = 0.f;
            mma_f16(d0, d1, d2, d3, A0[0][0], A0[0][1], A0[0][2], A0[0][3], a00, a01);
            mma_f16(d0, d1, d2, d3, A0[1][0], A0[1][1], A0[1][2], A0[1][3], a10, a11);
            mma_f16(d0, d1, d2, d3, A0[2][0], A0[2][1], A0[2][2], A0[2][3], a20, a21);
            mma_f16(d0, d1, d2, d3, A0[3][0], A0[3][1], A0[3][2], A0[3][3], a30, a31);
            const int nl = sub * 8 + 2 * tm4;
            float x20 = x2s[nl], x21 = x2s[nl + 1];
            best0 = fminf(best0, fmaxf(fmaf(d0, -2.0f, x20) + p2a, 0.0f));
            best0 = fminf(best0, fmaxf(fmaf(d1, -2.0f, x21) + p2a, 0.0f));
            best1 = fminf(best1, fmaxf(fmaf(d2, -2.0f, x20) + p2b, 0.0f));
            best1 = fminf(best1, fmaxf(fmaf(d3, -2.0f, x21) + p2b, 0.0f));
        }
        best0 = fminf(best0, __shfl_xor_sync(0xFFFFFFFFu, best0, 1));
        best0 = fminf(best0, __shfl_xor_sync(0xFFFFFFFFu, best0, 2));
        best1 = fminf(best1, __shfl_xor_sync(0xFFFFFFFFu, best1, 1));
        best1 = fminf(best1, __shfl_xor_sync(0xFFFFFFFFu, best1, 2));
    }

    /* publish prepass seed (1 lane per p-row group) */
    if (tm4 == 0) {
        atomicMin(&g_thr[bp0], __float_as_uint(best0));
        atomicMin(&g_thr[bp1], __float_as_uint(best1));
    }

    float thr0 = best0 + MARGIN;
    float thr1 = best1 + MARGIN;
    float thr0m = thr0 - p2a;
    float thr1m = thr1 - p2b;
    __syncthreads();            /* prepass reads done before restaging buf0 */

    stage(0);

    for (int it = 0; it < NCHUNK; it++) {
        /* fold in chip-wide best thresholds (independent loads, hoisted) */
        float gt0 = __uint_as_float(__ldcg((const unsigned*)&g_thr[bp0]));
        float gt1 = __uint_as_float(__ldcg((const unsigned*)&g_thr[bp1]));

        if (it + 1 < NCHUNK) {
            stage(it + 1);
            asm volatile("cp.async.wait_group 1;");
        } else {
            asm volatile("cp.async.wait_group 0;");
        }
        best0 = fminf(best0, gt0);
        best1 = fminf(best1, gt1);
        thr0 = best0 + MARGIN; thr0m = thr0 - p2a;
        thr1 = best1 + MARGIN; thr1m = thr1 - p2b;
        __syncthreads();

        const uint32_t sb = sbase + (it & 1) * BUFB;
        const float* x2s = (const float*)(sbuf + X2OFF + (it & 1) * 256);

        #pragma unroll 1
        for (int s2 = 0; s2 < 4; s2++) {
            const int sa = s2 * 2, sbn = s2 * 2 + 1;
            uint32_t aA = sb + (uint32_t)(sa * 8) * PITCHB + lrow;
            uint32_t aB = sb + (uint32_t)(sbn * 8) * PITCHB + lrow;
            uint32_t a00, a01, a10, a11, a20, a21, a30, a31;
            uint32_t b00, b01, b10, b11, b20, b21, b30, b31;
            ldmx4(aA,      a00, a01, a10, a11);
            ldmx4(aA + 64, a20, a21, a30, a31);
            ldmx4(aB,      b00, b01, b10, b11);
            ldmx4(aB + 64, b20, b21, b30, b31);

            float dA0 = 0.f, dA1 = 0.f, dA2 = 0.f, dA3 = 0.f;
            float dB0 = 0.f, dB1 = 0.f, dB2 = 0.f, dB3 = 0.f;
            mma_f16(dA0, dA1, dA2, dA3, A0[0][0], A0[0][1], A0[0][2], A0[0][3], a00, a01);
            mma_f16(dB0, dB1, dB2, dB3, A0[0][0], A0[0][1], A0[0][2], A0[0][3], b00, b01);
            mma_f16(dA0, dA1, dA2, dA3, A0[1][0], A0[1][1], A0[1][2], A0[1][3], a10, a11);
            mma_f16(dB0, dB1, dB2, dB3, A0[1][0], A0[1][1], A0[1][2], A0[1][3], b10, b11);
            mma_f16(dA0, dA1, dA2, dA3, A0[2][0], A0[2][1], A0[2][2], A0[2][3], a20, a21);
            mma_f16(dB0, dB1, dB2, dB3, A0[2][0], A0[2][1], A0[2][2], A0[2][3], b20, b21);
            mma_f16(dA0, dA1, dA2, dA3, A0[3][0], A0[3][1], A0[3][2], A0[3][3], a30, a31);
            mma_f16(dB0, dB1, dB2, dB3, A0[3][0], A0[3][1], A0[3][2], A0[3][3], b30, b31);

            #pragma unroll
            for (int half = 0; half < 2; half++) {
                const int sub = half ? sbn : sa;
                float d0 = half ? dB0 : dA0, d1 = half ? dB1 : dA1;
                float d2 = half ? dB2 : dA2, d3 = half ? dB3 : dA3;
                const int nl = sub * 8 + 2 * tm4;
                float x20 = x2s[nl];
                float x21 = x2s[nl + 1];
                float t0 = fmaf(d0, -2.0f, x20);
                float t1 = fmaf(d1, -2.0f, x21);
                float t2 = fmaf(d2, -2.0f, x20);
                float t3 = fmaf(d3, -2.0f, x21);
                if (fminf(t0, t1) < thr0m || fminf(t2, t3) < thr1m) {
                    const int nglob = n0 + it * CHN + nl;
                    float s00 = fmaxf(t0 + p2a, 0.0f);
                    float s01 = fmaxf(t1 + p2a, 0.0f);
                    float s10 = fmaxf(t2 + p2b, 0.0f);
                    float s11 = fmaxf(t3 + p2b, 0.0f);
                    if (s00 < thr0) {
                        if (s00 < best0) {
                            best0 = s00; thr0 = s00 + MARGIN; thr0m = thr0 - p2a;
                            atomicMin(&g_thr[bp0], __float_as_uint(best0));
                        }
                        int sl = atomicAdd(&g_cnt[bp0], 1);
                        if (sl < CAP) g_cand[bp0 * CAP + sl] = nglob;
                    }
                    if (s01 < thr0) {
                        if (s01 < best0) {
                            best0 = s01; thr0 = s01 + MARGIN; thr0m = thr0 - p2a;
                            atomicMin(&g_thr[bp0], __float_as_uint(best0));
                        }
                        int sl = atomicAdd(&g_cnt[bp0], 1);
                        if (sl < CAP) g_cand[bp0 * CAP + sl] = nglob + 1;
                    }
                    if (s10 < thr1) {
                        if (s10 < best1) {
                            best1 = s10; thr1 = s10 + MARGIN; thr1m = thr1 - p2b;
                            atomicMin(&g_thr[bp1], __float_as_uint(best1));
                        }
                        int sl = atomicAdd(&g_cnt[bp1], 1);
                        if (sl < CAP) g_cand[bp1 * CAP + sl] = nglob;
                    }
                    if (s11 < thr1) {
                        if (s11 < best1) {
                            best1 = s11; thr1 = s11 + MARGIN; thr1m = thr1 - p2b;
                            atomicMin(&g_thr[bp1], __float_as_uint(best1));
                        }
                        int sl = atomicAdd(&g_cnt[bp1], 1);
                        if (sl < CAP) g_cand[bp1 * CAP + sl] = nglob + 1;
                    }
                }
            }
        }
        __syncthreads();
    }
}

/* ------------------------------------------------------------------ */
/* refine: warp per (b,p); lane-per-candidate exact fp32 recompute. */
__global__ void refine_kernel(const float* __restrict__ x, float* __restrict__ out) {
    __shared__ float ps[8][DD];
    const int wid = threadIdx.x >> 5;
    const int lane = threadIdx.x & 31;
    const int pair = blockIdx.x * 8 + wid;
    const int bb = pair / PP, p = pair % PP;

    ((float2*)ps[wid])[lane] = ((const float2*)(g_pn + (size_t)p * DD))[lane];
    __syncwarp();
    const float p2 = g_p2[p];
    int cnt = g_cnt[pair];
    if (cnt > CAP) cnt = CAP;

    unsigned long long bestk = 0xFFFFFFFFFFFFFFFFull;
    for (int base = 0; base < cnt; base += 32) {
        int i = base + lane;
        if (i < cnt) {
            int n = g_cand[pair * CAP + i];
            const float4* xr = (const float4*)(x + ((size_t)bb * NN + n) * DD);
            float dot = 0.0f, x2 = 0.0f;
            #pragma unroll
            for (int c = 0; c < 16; c++) {
                float4 xv = __ldg(xr + c);
                float4 pv = ((const float4*)ps[wid])[c];
                dot = fmaf(xv.x, pv.x, dot); dot = fmaf(xv.y, pv.y, dot);
                dot = fmaf(xv.z, pv.z, dot); dot = fmaf(xv.w, pv.w, dot);
                x2 = fmaf(xv.x, xv.x, x2); x2 = fmaf(xv.y, xv.y, x2);
                x2 = fmaf(xv.z, xv.z, x2); x2 = fmaf(xv.w, xv.w, x2);
            }
            float sq = fmaxf(x2 - 2.0f * dot + p2, 0.0f);
            unsigned long long key =
                ((unsigned long long)__float_as_uint(sq) << 32) | (unsigned)n;
            if (key < bestk) bestk = key;
        }
    }
    #pragma unroll
    for (int o = 16; o; o >>= 1) {
        unsigned long long ok = __shfl_xor_sync(0xFFFFFFFFu, bestk, o);
        if (ok < bestk) bestk = ok;
    }
    if (lane == 0) {
        float sq = __uint_as_float((unsigned)(bestk >> 32));
        out[pair] = sqrtf(sq + 1e-8f);
        out[BB * PP + pair] = (float)(unsigned)(bestk & 0xFFFFFFFFu);
    }
}

extern "C" void kernel_launch(void* const* d_in, const int* in_sizes, int n_in,
                              void* d_out, int out_size) {
    const float* x = (const float*)d_in[0];
    const float* proto = (const float*)d_in[1];
    float* out = (float*)d_out;

    prep_conv_kernel<<<64 + (BB * NN) / 32, 256>>>(proto, x);
    dim3 grid(NSPLIT, PP / PT, BB);
    main_kernel<<<grid, 128>>>();
    refine_kernel<<<(BB * PP) / 8, 256>>>(x, out);
}